// round 8
// baseline (speedup 1.0000x reference)
#include <cuda_runtime.h>
#include <cstdint>

#define HIDDEN   1024
#define EMB      512
#define NUM_OPS  8
#define BATCH    16384

#define BM 128
#define BN 128
#define BK 32
#define PIPE 3
#define NTHREADS 256

#define AS_STRIDE 36                       // floats: 32 + 4 pad -> bank (4r+cc) bijection
#define BS_STRIDE 136                      // floats: 128 + 8 pad -> bank (8cc+r) bijection
#define A_STAGE_BYTES (BM * AS_STRIDE * 4) // 18432
#define B_STAGE_BYTES (BK * BS_STRIDE * 4) // 17408
#define STAGE_BYTES (A_STAGE_BYTES + B_STAGE_BYTES)
#define DYN_SMEM (PIPE * STAGE_BYTES)      // 107520

// ---- scratch (static device globals: no allocations allowed) ----
__device__ int   g_counts[NUM_OPS];
__device__ int   g_cursor[NUM_OPS];
__device__ int   g_offsets[NUM_OPS + 1];
__device__ int   g_perm[BATCH];
__device__ float g_xr[(size_t)BATCH * HIDDEN];            // tf32-rounded x
__device__ float g_embr[NUM_OPS * EMB];                   // tf32-rounded op_emb
__device__ float g_w1r[(size_t)NUM_OPS * 1536 * HIDDEN];  // tf32-rounded W1 [e][k][n]
__device__ float g_w2r[(size_t)NUM_OPS * 1024 * HIDDEN];  // tf32-rounded W2 [e][k][n]
__device__ float g_h[(size_t)BATCH * HIDDEN];             // layer-1 out (sorted, tf32-rounded)

// ---- helpers ----
__device__ __forceinline__ float to_tf32(float x) {
    float y; asm("cvt.rna.tf32.f32 %0, %1;" : "=f"(y) : "f"(x)); return y;
}
__device__ __forceinline__ uint32_t smem_u32(const void* p) {
    uint32_t a;
    asm("{ .reg .u64 t; cvta.to.shared.u64 t, %1; cvt.u32.u64 %0, t; }" : "=r"(a) : "l"(p));
    return a;
}
__device__ __forceinline__ void cp16(uint32_t s, const void* g) {
    asm volatile("cp.async.cg.shared.global [%0], [%1], 16;" :: "r"(s), "l"(g));
}
__device__ __forceinline__ void cp_commit() { asm volatile("cp.async.commit_group;"); }
template <int N> __device__ __forceinline__ void cp_wait() {
    asm volatile("cp.async.wait_group %0;" :: "n"(N));
}
__device__ __forceinline__ void mma_tf32(float c[4],
                                         uint32_t a0, uint32_t a1, uint32_t a2, uint32_t a3,
                                         uint32_t b0, uint32_t b1) {
    asm volatile(
        "mma.sync.aligned.m16n8k8.row.col.f32.tf32.tf32.f32 "
        "{%0,%1,%2,%3}, {%4,%5,%6,%7}, {%8,%9}, {%0,%1,%2,%3};"
        : "+f"(c[0]), "+f"(c[1]), "+f"(c[2]), "+f"(c[3])
        : "r"(a0), "r"(a1), "r"(a2), "r"(a3), "r"(b0), "r"(b1));
}

// ---- routing ----
__global__ void init_kernel() { if (threadIdx.x < NUM_OPS) g_counts[threadIdx.x] = 0; }
__global__ void hist_kernel(const int* __restrict__ ops) {
    int i = blockIdx.x * blockDim.x + threadIdx.x;
    if (i < BATCH) atomicAdd(&g_counts[ops[i]], 1);
}
__global__ void scan_kernel() {
    int acc = 0;
    for (int e = 0; e < NUM_OPS; ++e) { g_offsets[e] = acc; g_cursor[e] = acc; acc += g_counts[e]; }
    g_offsets[NUM_OPS] = acc;
}
__global__ void scatter_kernel(const int* __restrict__ ops) {
    int i = blockIdx.x * blockDim.x + threadIdx.x;
    if (i < BATCH) { int pos = atomicAdd(&g_cursor[ops[i]], 1); g_perm[pos] = i; }
}

// ---- tf32 pre-rounding (elementwise, vectorized) ----
__global__ void round_kernel(const float4* __restrict__ in, float4* __restrict__ out, int n4) {
    int i = blockIdx.x * blockDim.x + threadIdx.x;
    if (i < n4) {
        float4 v = in[i];
        v.x = to_tf32(v.x); v.y = to_tf32(v.y); v.z = to_tf32(v.z); v.w = to_tf32(v.w);
        out[i] = v;
    }
}

// ---- grouped GEMM, tf32 mma.sync, 3-stage cp.async pipeline ----
// LAYER 1: A = gather(g_xr / g_embr) [BM x 1536], B = g_w1r[e] [1536 x 128-slab]
//          -> relu(+b1), tf32-round, store g_h (sorted rows)
// LAYER 2: A = g_h, B = g_w2r[e] -> relu(+b2), scatter to out via g_perm
template <int LAYER>
__global__ __launch_bounds__(NTHREADS) void gemm_tc(
    const float* __restrict__ bias, float* __restrict__ out)
{
    constexpr int K  = (LAYER == 1) ? 1536 : 1024;
    constexpr int KT = K / BK;

    const int e = blockIdx.z;
    const int seg_lo = g_offsets[e];
    const int seg_hi = g_offsets[e + 1];
    const int row0 = seg_lo + blockIdx.y * BM;
    if (row0 >= seg_hi) return;
    const int n0 = blockIdx.x * BN;

    extern __shared__ char dyn[];
    const uint32_t sbase = smem_u32(dyn);

    const int tid  = threadIdx.x;
    const int lane = tid & 31;
    const int warp = tid >> 5;
    const int wm = (warp & 1) * 64;    // 2 warps along M
    const int wn = (warp >> 1) * 32;   // 4 warps along N
    const int r  = lane >> 2;
    const int cc = lane & 3;

    // A loader: one row per thread-pair; 4 x 16B chunks cover 32 floats of k
    const int arow_loc = tid >> 1;                 // 0..127
    const int ac0 = (tid & 1) * 4;                 // chunk base 0 or 4
    int arow = row0 + arow_loc;
    if (arow > seg_hi - 1) arow = seg_hi - 1;      // clamp; masked at store
    const float* Abase;
    if (LAYER == 1) Abase = g_xr + (size_t)g_perm[arow] * HIDDEN;
    else            Abase = g_h + (size_t)arow * HIDDEN;
    const float* Ebase = g_embr + e * EMB;
    const uint32_t a_soff = (uint32_t)(arow_loc * (AS_STRIDE * 4) + ac0 * 16);
    // A chunk j: gmem floats [ac0*4 + j*4, +4) ; smem bytes a_soff + j*16  (16B granules)

    // B loader: one k-row per 8 threads; 8 x 16B chunks per row, thread owns chunk bc + 8j? no:
    // thread bc owns chunks {bc*4 + j*32 floats}: gmem = Bbase + kb*H + j*32, smem = bc*16 + j*128B
    const int bk = tid >> 3;                       // 0..31
    const int bc = tid & 7;
    const float* Wr = (LAYER == 1) ? g_w1r : g_w2r;
    const float* Bbase = Wr + ((size_t)e * K + bk) * HIDDEN + n0 + bc * 4;
    const uint32_t b_soff = (uint32_t)(A_STAGE_BYTES + bk * (BS_STRIDE * 4) + bc * 16);

    auto load_stage = [&](int s) {
        const int kb = s * BK;
        const uint32_t st = sbase + (uint32_t)((s % PIPE) * STAGE_BYTES);
        const bool emb_stage = (LAYER == 1) && (kb >= HIDDEN);
        const float* asrc = emb_stage ? (Ebase + (kb - HIDDEN) + ac0 * 4)
                                      : (Abase + kb + ac0 * 4);
#pragma unroll
        for (int j = 0; j < 4; ++j) cp16(st + a_soff + j * 16u, asrc + j * 4);
        const float* bsrc = Bbase + (size_t)kb * HIDDEN;
#pragma unroll
        for (int j = 0; j < 4; ++j) cp16(st + b_soff + j * 128u, bsrc + j * 32);  // FIXED: 32 floats = 128 bytes
    };

    float c[4][4][4];
#pragma unroll
    for (int mt = 0; mt < 4; ++mt)
#pragma unroll
        for (int nt = 0; nt < 4; ++nt)
#pragma unroll
            for (int i = 0; i < 4; ++i) c[mt][nt][i] = 0.f;

    auto compute = [&](int buf) {
        const float* As = (const float*)(dyn + (size_t)buf * STAGE_BYTES);
        const float* Bs = (const float*)(dyn + (size_t)buf * STAGE_BYTES + A_STAGE_BYTES);
#pragma unroll
        for (int ks = 0; ks < 4; ++ks) {           // 4 x K=8 slices cover BK=32
            const int k8 = ks * 8;
            uint32_t af[4][4];
            uint32_t bf[4][2];
#pragma unroll
            for (int mt = 0; mt < 4; ++mt) {
                const int m = wm + mt * 16 + r;
                af[mt][0] = __float_as_uint(As[m * AS_STRIDE + k8 + cc]);
                af[mt][1] = __float_as_uint(As[(m + 8) * AS_STRIDE + k8 + cc]);
                af[mt][2] = __float_as_uint(As[m * AS_STRIDE + k8 + cc + 4]);
                af[mt][3] = __float_as_uint(As[(m + 8) * AS_STRIDE + k8 + cc + 4]);
            }
#pragma unroll
            for (int nt = 0; nt < 4; ++nt) {
                const int n = wn + nt * 8 + r;
                bf[nt][0] = __float_as_uint(Bs[(k8 + cc) * BS_STRIDE + n]);
                bf[nt][1] = __float_as_uint(Bs[(k8 + cc + 4) * BS_STRIDE + n]);
            }
#pragma unroll
            for (int mt = 0; mt < 4; ++mt)
#pragma unroll
                for (int nt = 0; nt < 4; ++nt)
                    mma_tf32(c[mt][nt], af[mt][0], af[mt][1], af[mt][2], af[mt][3],
                             bf[nt][0], bf[nt][1]);
        }
    };

    // prologue: 2 stages in flight
    load_stage(0); cp_commit();
    load_stage(1); cp_commit();

    for (int kt = 0; kt < KT; ++kt) {
        cp_wait<1>();                 // stage kt resident (always exactly 2 groups pending)
        __syncthreads();              // all threads see stage kt; all done reading buf (kt+2)%3
        if (kt + 2 < KT) load_stage(kt + 2);
        cp_commit();                  // commit (possibly empty) keeps group counts uniform
        compute(kt % PIPE);
    }

    // epilogue: bias + relu (+ tf32 round for layer 1) + masked store
    const float* brow = bias + e * HIDDEN;
#pragma unroll
    for (int mt = 0; mt < 4; ++mt) {
        const int rbase = row0 + wm + mt * 16 + r;
#pragma unroll
        for (int half = 0; half < 2; ++half) {
            const int row = rbase + half * 8;
            if (row >= seg_hi) continue;
            float* yrow;
            if (LAYER == 1) yrow = g_h + (size_t)row * HIDDEN;
            else            yrow = out + (size_t)g_perm[row] * HIDDEN;
#pragma unroll
            for (int nt = 0; nt < 4; ++nt) {
                const int col = n0 + wn + nt * 8 + 2 * cc;
                float v0 = c[mt][nt][half * 2 + 0] + __ldg(brow + col);
                float v1 = c[mt][nt][half * 2 + 1] + __ldg(brow + col + 1);
                v0 = v0 > 0.f ? v0 : 0.f;
                v1 = v1 > 0.f ? v1 : 0.f;
                if (LAYER == 1) { v0 = to_tf32(v0); v1 = to_tf32(v1); }
                *(float2*)(yrow + col) = make_float2(v0, v1);
            }
        }
    }
}

extern "C" void kernel_launch(void* const* d_in, const int* in_sizes, int n_in,
                              void* d_out, int out_size) {
    const float* x      = (const float*)d_in[0];
    const int*   ops    = (const int*)  d_in[1];
    const float* op_emb = (const float*)d_in[2];
    const float* W1     = (const float*)d_in[3];
    const float* b1     = (const float*)d_in[4];
    const float* W2     = (const float*)d_in[5];
    const float* b2     = (const float*)d_in[6];
    float* out = (float*)d_out;

    // idempotent, capture-legal host-side attribute set (no static guards allowed)
    cudaFuncSetAttribute(gemm_tc<1>, cudaFuncAttributeMaxDynamicSharedMemorySize, DYN_SMEM);
    cudaFuncSetAttribute(gemm_tc<2>, cudaFuncAttributeMaxDynamicSharedMemorySize, DYN_SMEM);

    // routing
    init_kernel<<<1, 32>>>();
    hist_kernel<<<BATCH / 256, 256>>>(ops);
    scan_kernel<<<1, 1>>>();
    scatter_kernel<<<BATCH / 256, 256>>>(ops);

    // tf32 pre-rounding (removes cvt from GEMM hot loops)
    {
        float* xr;  cudaGetSymbolAddress((void**)&xr,  g_xr);
        float* er;  cudaGetSymbolAddress((void**)&er,  g_embr);
        float* w1r; cudaGetSymbolAddress((void**)&w1r, g_w1r);
        float* w2r; cudaGetSymbolAddress((void**)&w2r, g_w2r);
        int n4;
        n4 = BATCH * HIDDEN / 4;
        round_kernel<<<(n4 + 255) / 256, 256>>>((const float4*)x, (float4*)xr, n4);
        n4 = NUM_OPS * EMB / 4;
        round_kernel<<<(n4 + 255) / 256, 256>>>((const float4*)op_emb, (float4*)er, n4);
        n4 = NUM_OPS * 1536 * HIDDEN / 4;
        round_kernel<<<(n4 + 255) / 256, 256>>>((const float4*)W1, (float4*)w1r, n4);
        n4 = NUM_OPS * 1024 * HIDDEN / 4;
        round_kernel<<<(n4 + 255) / 256, 256>>>((const float4*)W2, (float4*)w2r, n4);
    }

    dim3 grid(HIDDEN / BN, BATCH / BM, NUM_OPS);
    gemm_tc<1><<<grid, NTHREADS, DYN_SMEM>>>(b1, nullptr);
    gemm_tc<2><<<grid, NTHREADS, DYN_SMEM>>>(b2, out);
}

// round 10
// speedup vs baseline: 1.5029x; 1.5029x over previous
#include <cuda_runtime.h>
#include <cuda_fp16.h>
#include <cstdint>

#define HIDDEN   1024
#define EMB      512
#define NUM_OPS  8
#define BATCH    16384

#define BM 128
#define BN 128
#define BK 32
#define PIPE 3
#define NTHREADS 256

// smem strides in halves: 32 + 8 pad = 40 halves = 80 bytes/row
// word-bank = (20*row + cc) & 31 -> bijection over a warp's 32 lanes (verified)
#define ROW_BYTES 80
#define A_STAGE_BYTES (BM * ROW_BYTES)     // 10240
#define B_STAGE_BYTES (BN * ROW_BYTES)     // 10240 (B stored [n][k])
#define STAGE_BYTES (A_STAGE_BYTES + B_STAGE_BYTES)
#define DYN_SMEM (PIPE * STAGE_BYTES)      // 61440

// ---- scratch (static device globals: no allocations allowed) ----
__device__ int    g_counts[NUM_OPS];
__device__ int    g_cursor[NUM_OPS];
__device__ int    g_offsets[NUM_OPS + 1];
__device__ int    g_perm[BATCH];
__device__ __half g_xh[(size_t)BATCH * HIDDEN];            // fp16 x
__device__ __half g_embh[NUM_OPS * EMB];                   // fp16 op_emb
__device__ __half g_w1t[(size_t)NUM_OPS * HIDDEN * 1536];  // fp16 W1^T [e][n][k]
__device__ __half g_w2t[(size_t)NUM_OPS * HIDDEN * 1024];  // fp16 W2^T [e][n][k]
__device__ __half g_h[(size_t)BATCH * HIDDEN];             // layer-1 out (sorted, fp16)

// ---- helpers ----
__device__ __forceinline__ uint32_t smem_u32(const void* p) {
    uint32_t a;
    asm("{ .reg .u64 t; cvta.to.shared.u64 t, %1; cvt.u32.u64 %0, t; }" : "=r"(a) : "l"(p));
    return a;
}
__device__ __forceinline__ void cp16(uint32_t s, const void* g) {
    asm volatile("cp.async.cg.shared.global [%0], [%1], 16;" :: "r"(s), "l"(g));
}
__device__ __forceinline__ void cp_commit() { asm volatile("cp.async.commit_group;"); }
template <int N> __device__ __forceinline__ void cp_wait() {
    asm volatile("cp.async.wait_group %0;" :: "n"(N));
}
__device__ __forceinline__ void mma_f16(float c[4],
                                        uint32_t a0, uint32_t a1, uint32_t a2, uint32_t a3,
                                        uint32_t b0, uint32_t b1) {
    asm volatile(
        "mma.sync.aligned.m16n8k16.row.col.f32.f16.f16.f32 "
        "{%0,%1,%2,%3}, {%4,%5,%6,%7}, {%8,%9}, {%0,%1,%2,%3};"
        : "+f"(c[0]), "+f"(c[1]), "+f"(c[2]), "+f"(c[3])
        : "r"(a0), "r"(a1), "r"(a2), "r"(a3), "r"(b0), "r"(b1));
}
__device__ __forceinline__ uint32_t lds_u32(const char* base, uint32_t off) {
    return *(const uint32_t*)(base + off);
}

// ---- routing ----
__global__ void init_kernel() { if (threadIdx.x < NUM_OPS) g_counts[threadIdx.x] = 0; }
__global__ void hist_kernel(const int* __restrict__ ops) {
    int i = blockIdx.x * blockDim.x + threadIdx.x;
    if (i < BATCH) atomicAdd(&g_counts[ops[i]], 1);
}
__global__ void scan_kernel() {
    int acc = 0;
    for (int e = 0; e < NUM_OPS; ++e) { g_offsets[e] = acc; g_cursor[e] = acc; acc += g_counts[e]; }
    g_offsets[NUM_OPS] = acc;
}
__global__ void scatter_kernel(const int* __restrict__ ops) {
    int i = blockIdx.x * blockDim.x + threadIdx.x;
    if (i < BATCH) { int pos = atomicAdd(&g_cursor[ops[i]], 1); g_perm[pos] = i; }
}

// ---- fp16 convert (elementwise, vectorized) ----
__global__ void cvt_kernel(const float4* __restrict__ in, uint2* __restrict__ out, int n4) {
    int i = blockIdx.x * blockDim.x + threadIdx.x;
    if (i < n4) {
        float4 v = in[i];
        __half2 h01 = __floats2half2_rn(v.x, v.y);
        __half2 h23 = __floats2half2_rn(v.z, v.w);
        uint2 o;
        o.x = *(uint32_t*)&h01;
        o.y = *(uint32_t*)&h23;
        out[i] = o;
    }
}

// ---- W [e][k][n] fp32 -> Wt [e][n][k] fp16 (32x32 tiles) ----
__global__ void transpose_cvt_kernel(const float* __restrict__ W, __half* __restrict__ Wt, int K) {
    __shared__ float t[32][33];
    const int e = blockIdx.z;
    const int n0 = blockIdx.x * 32, k0 = blockIdx.y * 32;
    const float* Wb = W + (size_t)e * K * HIDDEN;
    __half* Wtb = Wt + (size_t)e * HIDDEN * K;
    const int tid = threadIdx.x;   // 256
#pragma unroll
    for (int i = 0; i < 4; ++i) {
        int idx = tid + 256 * i;
        int n = idx & 31, k = idx >> 5;
        t[k][n] = Wb[(size_t)(k0 + k) * HIDDEN + n0 + n];
    }
    __syncthreads();
#pragma unroll
    for (int i = 0; i < 2; ++i) {
        int idx = tid + 256 * i;
        int nl = idx >> 4, p = idx & 15;
        __half2 h = __floats2half2_rn(t[2 * p][nl], t[2 * p + 1][nl]);
        *(__half2*)(Wtb + (size_t)(n0 + nl) * K + k0 + 2 * p) = h;
    }
}

// ---- grouped GEMM, fp16 mma.sync m16n8k16 (fp32 accum), 3-stage cp.async ----
// LAYER 1: A = gather(g_xh / g_embh) [BM x 1536], B = g_w1t[e] -> relu(+b1) -> g_h fp16
// LAYER 2: A = g_h, B = g_w2t[e] -> relu(+b2) -> scatter fp32 out via g_perm
template <int LAYER>
__global__ __launch_bounds__(NTHREADS, 2) void gemm_tc(
    const float* __restrict__ bias, float* __restrict__ out)
{
    constexpr int K  = (LAYER == 1) ? 1536 : 1024;
    constexpr int KT = K / BK;

    const int e = blockIdx.z;
    const int seg_lo = g_offsets[e];
    const int seg_hi = g_offsets[e + 1];
    const int row0 = seg_lo + blockIdx.y * BM;
    if (row0 >= seg_hi) return;
    const int n0 = blockIdx.x * BN;

    extern __shared__ char dyn[];
    const uint32_t sbase = smem_u32(dyn);

    const int tid  = threadIdx.x;
    const int lane = tid & 31;
    const int warp = tid >> 5;
    const int wm = (warp & 1) * 64;    // 2 warps along M
    const int wn = (warp >> 1) * 32;   // 4 warps along N
    const int r  = lane >> 2;
    const int cc = lane & 3;

    // A loader: row = tid>>1 (0..127), two 16B chunks (16 halves) per thread
    const int arow_loc = tid >> 1;
    const int ac0 = (tid & 1) * 2;                 // chunk base 0 or 2 (of 4 per 32-half row)
    int arow = row0 + arow_loc;
    if (arow > seg_hi - 1) arow = seg_hi - 1;      // clamp; masked at store
    const __half* Abase;
    if (LAYER == 1) Abase = g_xh + (size_t)g_perm[arow] * HIDDEN;
    else            Abase = g_h + (size_t)arow * HIDDEN;
    const __half* Ebase = g_embh + e * EMB;
    const uint32_t a_soff = (uint32_t)(arow_loc * ROW_BYTES + ac0 * 16);

    // B loader: n-row = tid>>1, two 16B chunks per thread; B stored [n][k] K-major
    const __half* Wt = (LAYER == 1) ? g_w1t : g_w2t;
    const __half* Bbase = Wt + ((size_t)e * HIDDEN + n0 + arow_loc) * K + ac0 * 8;
    const uint32_t b_soff = (uint32_t)(A_STAGE_BYTES + arow_loc * ROW_BYTES + ac0 * 16);

    auto load_stage = [&](int s) {
        const int kb = s * BK;
        const uint32_t st = sbase + (uint32_t)((s % PIPE) * STAGE_BYTES);
        const bool emb_stage = (LAYER == 1) && (kb >= HIDDEN);
        const __half* asrc = emb_stage ? (Ebase + (kb - HIDDEN) + ac0 * 8)
                                       : (Abase + kb + ac0 * 8);
#pragma unroll
        for (int j = 0; j < 2; ++j) cp16(st + a_soff + j * 16u, asrc + j * 8);
        const __half* bsrc = Bbase + kb;
#pragma unroll
        for (int j = 0; j < 2; ++j) cp16(st + b_soff + j * 16u, bsrc + j * 8);
    };

    float c[4][4][4];
#pragma unroll
    for (int mt = 0; mt < 4; ++mt)
#pragma unroll
        for (int nt = 0; nt < 4; ++nt)
#pragma unroll
            for (int i = 0; i < 4; ++i) c[mt][nt][i] = 0.f;

    auto compute = [&](int buf) {
        const char* As = dyn + (size_t)buf * STAGE_BYTES;
        const char* Bs = As + A_STAGE_BYTES;
#pragma unroll
        for (int ks = 0; ks < 2; ++ks) {           // 2 x K=16 slices cover BK=32
            const uint32_t kb = (uint32_t)(ks * 32 + 4 * cc);   // byte offset of (k = 16*ks + 2*cc)
            uint32_t af[4][4];
            uint32_t bf[4][2];
#pragma unroll
            for (int mt = 0; mt < 4; ++mt) {
                const uint32_t m = (uint32_t)(wm + mt * 16 + r);
                af[mt][0] = lds_u32(As, m * ROW_BYTES + kb);            // (r,      2cc..)
                af[mt][1] = lds_u32(As, (m + 8) * ROW_BYTES + kb);      // (r+8,    2cc..)
                af[mt][2] = lds_u32(As, m * ROW_BYTES + kb + 16u);      // (r,   2cc+8..)
                af[mt][3] = lds_u32(As, (m + 8) * ROW_BYTES + kb + 16u);
            }
#pragma unroll
            for (int nt = 0; nt < 4; ++nt) {
                const uint32_t n = (uint32_t)(wn + nt * 8 + r);
                bf[nt][0] = lds_u32(Bs, n * ROW_BYTES + kb);            // (2cc..,   n)
                bf[nt][1] = lds_u32(Bs, n * ROW_BYTES + kb + 16u);      // (2cc+8.., n)
            }
#pragma unroll
            for (int mt = 0; mt < 4; ++mt)
#pragma unroll
                for (int nt = 0; nt < 4; ++nt)
                    mma_f16(c[mt][nt], af[mt][0], af[mt][1], af[mt][2], af[mt][3],
                            bf[nt][0], bf[nt][1]);
        }
    };

    // prologue: 2 stages in flight
    load_stage(0); cp_commit();
    load_stage(1); cp_commit();

    for (int kt = 0; kt < KT; ++kt) {
        cp_wait<1>();                 // stage kt resident (always exactly 2 groups pending)
        __syncthreads();              // all threads see stage kt; all done reading buf (kt+2)%3
        if (kt + 2 < KT) load_stage(kt + 2);
        cp_commit();                  // uniform (possibly empty) commit keeps group counts fixed
        compute(kt % PIPE);
    }

    // epilogue: bias + relu; layer1 -> fp16 g_h, layer2 -> fp32 scatter
    const float* brow = bias + e * HIDDEN;
#pragma unroll
    for (int mt = 0; mt < 4; ++mt) {
        const int rbase = row0 + wm + mt * 16 + r;
#pragma unroll
        for (int half = 0; half < 2; ++half) {
            const int row = rbase + half * 8;
            if (row >= seg_hi) continue;
#pragma unroll
            for (int nt = 0; nt < 4; ++nt) {
                const int col = n0 + wn + nt * 8 + 2 * cc;
                float v0 = c[mt][nt][half * 2 + 0] + __ldg(brow + col);
                float v1 = c[mt][nt][half * 2 + 1] + __ldg(brow + col + 1);
                v0 = v0 > 0.f ? v0 : 0.f;
                v1 = v1 > 0.f ? v1 : 0.f;
                if (LAYER == 1) {
                    __half2 h = __floats2half2_rn(v0, v1);
                    *(__half2*)(g_h + (size_t)row * HIDDEN + col) = h;
                } else {
                    *(float2*)(out + (size_t)g_perm[row] * HIDDEN + col) = make_float2(v0, v1);
                }
            }
        }
    }
}

extern "C" void kernel_launch(void* const* d_in, const int* in_sizes, int n_in,
                              void* d_out, int out_size) {
    const float* x      = (const float*)d_in[0];
    const int*   ops    = (const int*)  d_in[1];
    const float* op_emb = (const float*)d_in[2];
    const float* W1     = (const float*)d_in[3];
    const float* b1     = (const float*)d_in[4];
    const float* W2     = (const float*)d_in[5];
    const float* b2     = (const float*)d_in[6];
    float* out = (float*)d_out;

    cudaFuncSetAttribute(gemm_tc<1>, cudaFuncAttributeMaxDynamicSharedMemorySize, DYN_SMEM);
    cudaFuncSetAttribute(gemm_tc<2>, cudaFuncAttributeMaxDynamicSharedMemorySize, DYN_SMEM);

    // routing
    init_kernel<<<1, 32>>>();
    hist_kernel<<<BATCH / 256, 256>>>(ops);
    scan_kernel<<<1, 1>>>();
    scatter_kernel<<<BATCH / 256, 256>>>(ops);

    // fp16 conversion + weight transpose
    {
        __half* xh;  cudaGetSymbolAddress((void**)&xh,  g_xh);
        __half* eh;  cudaGetSymbolAddress((void**)&eh,  g_embh);
        __half* w1t; cudaGetSymbolAddress((void**)&w1t, g_w1t);
        __half* w2t; cudaGetSymbolAddress((void**)&w2t, g_w2t);
        int n4;
        n4 = BATCH * HIDDEN / 4;
        cvt_kernel<<<(n4 + 255) / 256, 256>>>((const float4*)x, (uint2*)xh, n4);
        n4 = NUM_OPS * EMB / 4;
        cvt_kernel<<<(n4 + 255) / 256, 256>>>((const float4*)op_emb, (uint2*)eh, n4);
        transpose_cvt_kernel<<<dim3(HIDDEN / 32, 1536 / 32, NUM_OPS), 256>>>(W1, w1t, 1536);
        transpose_cvt_kernel<<<dim3(HIDDEN / 32, 1024 / 32, NUM_OPS), 256>>>(W2, w2t, 1024);
    }

    dim3 grid(HIDDEN / BN, BATCH / BM, NUM_OPS);
    gemm_tc<1><<<grid, NTHREADS, DYN_SMEM>>>(b1, nullptr);
    gemm_tc<2><<<grid, NTHREADS, DYN_SMEM>>>(b2, out);
}

// round 12
// speedup vs baseline: 1.5980x; 1.0633x over previous
#include <cuda_runtime.h>
#include <cuda_fp16.h>
#include <cstdint>

#define HIDDEN   1024
#define EMB      512
#define NUM_OPS  8
#define BATCH    16384

#define BM 128
#define BN 128
#define BK 32
#define PIPE 4
#define NTHREADS 256

// smem row stride: 32 halves + 8 pad = 40 halves = 80 bytes (16B-aligned)
// LDSM 8-row phase: row i starts at word-bank (20*i)%32 -> 8 rows x 4 words tile all 32 banks
#define ROW_BYTES 80
#define A_STAGE_BYTES (BM * ROW_BYTES)     // 10240
#define B_STAGE_BYTES (BN * ROW_BYTES)     // 10240 (B stored [n][k])
#define STAGE_BYTES (A_STAGE_BYTES + B_STAGE_BYTES)
#define DYN_SMEM (PIPE * STAGE_BYTES)      // 81920 -> 2 CTAs/SM

// ---- scratch (static device globals: no allocations allowed) ----
__device__ int    g_counts[NUM_OPS];
__device__ int    g_cursor[NUM_OPS];
__device__ int    g_offsets[NUM_OPS + 1];
__device__ int    g_perm[BATCH];
__device__ __half g_xh[(size_t)BATCH * HIDDEN];            // fp16 x
__device__ __half g_embh[NUM_OPS * EMB];                   // fp16 op_emb
__device__ __half g_w1t[(size_t)NUM_OPS * HIDDEN * 1536];  // fp16 W1^T [e][n][k]
__device__ __half g_w2t[(size_t)NUM_OPS * HIDDEN * 1024];  // fp16 W2^T [e][n][k]
__device__ __half g_h[(size_t)BATCH * HIDDEN];             // layer-1 out (sorted, fp16)

// ---- helpers ----
__device__ __forceinline__ uint32_t smem_u32(const void* p) {
    uint32_t a;
    asm("{ .reg .u64 t; cvta.to.shared.u64 t, %1; cvt.u32.u64 %0, t; }" : "=r"(a) : "l"(p));
    return a;
}
__device__ __forceinline__ void cp16(uint32_t s, const void* g) {
    asm volatile("cp.async.cg.shared.global [%0], [%1], 16;" :: "r"(s), "l"(g));
}
__device__ __forceinline__ void cp_commit() { asm volatile("cp.async.commit_group;"); }
template <int N> __device__ __forceinline__ void cp_wait() {
    asm volatile("cp.async.wait_group %0;" :: "n"(N));
}
__device__ __forceinline__ void ldsm4(uint32_t& d0, uint32_t& d1, uint32_t& d2, uint32_t& d3,
                                      uint32_t addr) {
    asm volatile("ldmatrix.sync.aligned.m8n8.x4.shared.b16 {%0,%1,%2,%3}, [%4];"
                 : "=r"(d0), "=r"(d1), "=r"(d2), "=r"(d3) : "r"(addr));
}
__device__ __forceinline__ void mma_f16(float c[4],
                                        uint32_t a0, uint32_t a1, uint32_t a2, uint32_t a3,
                                        uint32_t b0, uint32_t b1) {
    asm volatile(
        "mma.sync.aligned.m16n8k16.row.col.f32.f16.f16.f32 "
        "{%0,%1,%2,%3}, {%4,%5,%6,%7}, {%8,%9}, {%0,%1,%2,%3};"
        : "+f"(c[0]), "+f"(c[1]), "+f"(c[2]), "+f"(c[3])
        : "r"(a0), "r"(a1), "r"(a2), "r"(a3), "r"(b0), "r"(b1));
}

// ---- routing ----
__global__ void init_kernel() { if (threadIdx.x < NUM_OPS) g_counts[threadIdx.x] = 0; }
__global__ void hist_kernel(const int* __restrict__ ops) {
    int i = blockIdx.x * blockDim.x + threadIdx.x;
    if (i < BATCH) atomicAdd(&g_counts[ops[i]], 1);
}
__global__ void scan_kernel() {
    int acc = 0;
    for (int e = 0; e < NUM_OPS; ++e) { g_offsets[e] = acc; g_cursor[e] = acc; acc += g_counts[e]; }
    g_offsets[NUM_OPS] = acc;
}
__global__ void scatter_kernel(const int* __restrict__ ops) {
    int i = blockIdx.x * blockDim.x + threadIdx.x;
    if (i < BATCH) { int pos = atomicAdd(&g_cursor[ops[i]], 1); g_perm[pos] = i; }
}

// ---- fp16 convert (elementwise, vectorized) ----
__global__ void cvt_kernel(const float4* __restrict__ in, uint2* __restrict__ out, int n4) {
    int i = blockIdx.x * blockDim.x + threadIdx.x;
    if (i < n4) {
        float4 v = in[i];
        __half2 h01 = __floats2half2_rn(v.x, v.y);
        __half2 h23 = __floats2half2_rn(v.z, v.w);
        uint2 o;
        o.x = *(uint32_t*)&h01;
        o.y = *(uint32_t*)&h23;
        out[i] = o;
    }
}

// ---- W [e][k][n] fp32 -> Wt [e][n][k] fp16 (32x32 tiles) ----
__global__ void transpose_cvt_kernel(const float* __restrict__ W, __half* __restrict__ Wt, int K) {
    __shared__ float t[32][33];
    const int e = blockIdx.z;
    const int n0 = blockIdx.x * 32, k0 = blockIdx.y * 32;
    const float* Wb = W + (size_t)e * K * HIDDEN;
    __half* Wtb = Wt + (size_t)e * HIDDEN * K;
    const int tid = threadIdx.x;   // 256
#pragma unroll
    for (int i = 0; i < 4; ++i) {
        int idx = tid + 256 * i;
        int n = idx & 31, k = idx >> 5;
        t[k][n] = Wb[(size_t)(k0 + k) * HIDDEN + n0 + n];
    }
    __syncthreads();
#pragma unroll
    for (int i = 0; i < 2; ++i) {
        int idx = tid + 256 * i;
        int nl = idx >> 4, p = idx & 15;
        __half2 h = __floats2half2_rn(t[2 * p][nl], t[2 * p + 1][nl]);
        *(__half2*)(Wtb + (size_t)(n0 + nl) * K + k0 + 2 * p) = h;
    }
}

// ---- grouped GEMM, fp16 mma m16n8k16 (fp32 accum), 4-stage cp.async, ldmatrix ----
template <int LAYER>
__global__ __launch_bounds__(NTHREADS, 2) void gemm_tc(
    const float* __restrict__ bias, float* __restrict__ out)
{
    constexpr int K  = (LAYER == 1) ? 1536 : 1024;
    constexpr int KT = K / BK;

    const int e = blockIdx.z;
    const int seg_lo = g_offsets[e];
    const int seg_hi = g_offsets[e + 1];
    const int row0 = seg_lo + blockIdx.y * BM;
    if (row0 >= seg_hi) return;
    const int n0 = blockIdx.x * BN;

    extern __shared__ char dyn[];
    const uint32_t sbase = smem_u32(dyn);

    const int tid  = threadIdx.x;
    const int lane = tid & 31;
    const int warp = tid >> 5;
    const int wm = (warp & 1) * 64;    // 2 warps along M
    const int wn = (warp >> 1) * 32;   // 4 warps along N
    const int r  = lane >> 2;
    const int cc = lane & 3;

    // A loader: row = tid>>1 (0..127), two 16B chunks (16 halves) per thread
    const int arow_loc = tid >> 1;
    const int ac0 = (tid & 1) * 2;                 // chunk base 0 or 2 (of 4 per 32-half row)
    int arow = row0 + arow_loc;
    if (arow > seg_hi - 1) arow = seg_hi - 1;      // clamp; masked at store
    const __half* Abase;
    if (LAYER == 1) Abase = g_xh + (size_t)g_perm[arow] * HIDDEN;
    else            Abase = g_h + (size_t)arow * HIDDEN;
    const __half* Ebase = g_embh + e * EMB;
    const uint32_t a_soff = (uint32_t)(arow_loc * ROW_BYTES + ac0 * 16);

    // B loader: n-row = tid>>1, two 16B chunks per thread; B stored [n][k] K-major
    const __half* Wt = (LAYER == 1) ? g_w1t : g_w2t;
    const __half* Bbase = Wt + ((size_t)e * HIDDEN + n0 + arow_loc) * K + ac0 * 8;
    const uint32_t b_soff = (uint32_t)(A_STAGE_BYTES + arow_loc * ROW_BYTES + ac0 * 16);

    auto load_stage = [&](int s) {
        const int kb = s * BK;
        const uint32_t st = sbase + (uint32_t)((s % PIPE) * STAGE_BYTES);
        const bool emb_stage = (LAYER == 1) && (kb >= HIDDEN);
        const __half* asrc = emb_stage ? (Ebase + (kb - HIDDEN) + ac0 * 8)
                                       : (Abase + kb + ac0 * 8);
#pragma unroll
        for (int j = 0; j < 2; ++j) cp16(st + a_soff + j * 16u, asrc + j * 8);
        const __half* bsrc = Bbase + kb;
#pragma unroll
        for (int j = 0; j < 2; ++j) cp16(st + b_soff + j * 16u, bsrc + j * 8);
    };

    // ldmatrix per-thread base offsets (within a stage)
    // A x4 (tile mt): d0=(rows m+0..7,k0-7) d1=(m+8..15,k0-7) d2=(m+0..7,k8-15) d3=(m+8..15,k8-15)
    const uint32_t a_lds = (uint32_t)((wm + (lane & 15)) * ROW_BYTES + ((lane >> 4) & 1) * 16);
    // B x4 (pair p): d0=(n=wn+16p+0..7,k0-7) d1=(same n,k8-15) d2=(n+8..15,k0-7) d3=(n+8..15,k8-15)
    const uint32_t b_lds = (uint32_t)(A_STAGE_BYTES +
                                      (wn + ((lane >> 4) & 1) * 8 + (lane & 7)) * ROW_BYTES +
                                      ((lane >> 3) & 1) * 16);

    float c[4][4][4];
#pragma unroll
    for (int mt = 0; mt < 4; ++mt)
#pragma unroll
        for (int nt = 0; nt < 4; ++nt)
#pragma unroll
            for (int i = 0; i < 4; ++i) c[mt][nt][i] = 0.f;

    auto compute = [&](int buf) {
        const uint32_t sb = sbase + (uint32_t)buf * STAGE_BYTES;
#pragma unroll
        for (int ks = 0; ks < 2; ++ks) {           // 2 x K=16 slices cover BK=32
            const uint32_t ko = (uint32_t)(ks * 32);
            uint32_t af[4][4];
            uint32_t bf[4][2];
#pragma unroll
            for (int mt = 0; mt < 4; ++mt)
                ldsm4(af[mt][0], af[mt][1], af[mt][2], af[mt][3],
                      sb + a_lds + (uint32_t)(mt * 16 * ROW_BYTES) + ko);
#pragma unroll
            for (int p = 0; p < 2; ++p)
                ldsm4(bf[2 * p][0], bf[2 * p][1], bf[2 * p + 1][0], bf[2 * p + 1][1],
                      sb + b_lds + (uint32_t)(p * 16 * ROW_BYTES) + ko);
#pragma unroll
            for (int mt = 0; mt < 4; ++mt)
#pragma unroll
                for (int nt = 0; nt < 4; ++nt)
                    mma_f16(c[mt][nt], af[mt][0], af[mt][1], af[mt][2], af[mt][3],
                            bf[nt][0], bf[nt][1]);
        }
    };

    // prologue: 3 stages in flight
    load_stage(0); cp_commit();
    load_stage(1); cp_commit();
    load_stage(2); cp_commit();

    for (int kt = 0; kt < KT; ++kt) {
        cp_wait<2>();                 // stage kt resident; kt+1, kt+2 still in flight
        __syncthreads();              // all warps see stage kt; all done reading buf (kt+3)%4
        if (kt + 3 < KT) load_stage(kt + 3);
        cp_commit();                  // uniform (possibly empty) commit keeps group counts fixed
        compute(kt % PIPE);
    }

    // epilogue: bias + relu; layer1 -> fp16 g_h, layer2 -> fp32 scatter
    const float* brow = bias + e * HIDDEN;
#pragma unroll
    for (int mt = 0; mt < 4; ++mt) {
        const int rbase = row0 + wm + mt * 16 + r;
#pragma unroll
        for (int half = 0; half < 2; ++half) {
            const int row = rbase + half * 8;
            if (row >= seg_hi) continue;
#pragma unroll
            for (int nt = 0; nt < 4; ++nt) {
                const int col = n0 + wn + nt * 8 + 2 * cc;
                float v0 = c[mt][nt][half * 2 + 0] + __ldg(brow + col);
                float v1 = c[mt][nt][half * 2 + 1] + __ldg(brow + col + 1);
                v0 = v0 > 0.f ? v0 : 0.f;
                v1 = v1 > 0.f ? v1 : 0.f;
                if (LAYER == 1) {
                    __half2 h = __floats2half2_rn(v0, v1);
                    *(__half2*)(g_h + (size_t)row * HIDDEN + col) = h;
                } else {
                    *(float2*)(out + (size_t)g_perm[row] * HIDDEN + col) = make_float2(v0, v1);
                }
            }
        }
    }
}

extern "C" void kernel_launch(void* const* d_in, const int* in_sizes, int n_in,
                              void* d_out, int out_size) {
    const float* x      = (const float*)d_in[0];
    const int*   ops    = (const int*)  d_in[1];
    const float* op_emb = (const float*)d_in[2];
    const float* W1     = (const float*)d_in[3];
    const float* b1     = (const float*)d_in[4];
    const float* W2     = (const float*)d_in[5];
    const float* b2     = (const float*)d_in[6];
    float* out = (float*)d_out;

    cudaFuncSetAttribute(gemm_tc<1>, cudaFuncAttributeMaxDynamicSharedMemorySize, DYN_SMEM);
    cudaFuncSetAttribute(gemm_tc<2>, cudaFuncAttributeMaxDynamicSharedMemorySize, DYN_SMEM);

    // routing
    init_kernel<<<1, 32>>>();
    hist_kernel<<<BATCH / 256, 256>>>(ops);
    scan_kernel<<<1, 1>>>();
    scatter_kernel<<<BATCH / 256, 256>>>(ops);

    // fp16 conversion + weight transpose
    {
        __half* xh;  cudaGetSymbolAddress((void**)&xh,  g_xh);
        __half* eh;  cudaGetSymbolAddress((void**)&eh,  g_embh);
        __half* w1t; cudaGetSymbolAddress((void**)&w1t, g_w1t);
        __half* w2t; cudaGetSymbolAddress((void**)&w2t, g_w2t);
        int n4;
        n4 = BATCH * HIDDEN / 4;
        cvt_kernel<<<(n4 + 255) / 256, 256>>>((const float4*)x, (uint2*)xh, n4);
        n4 = NUM_OPS * EMB / 4;
        cvt_kernel<<<(n4 + 255) / 256, 256>>>((const float4*)op_emb, (uint2*)eh, n4);
        transpose_cvt_kernel<<<dim3(HIDDEN / 32, 1536 / 32, NUM_OPS), 256>>>(W1, w1t, 1536);
        transpose_cvt_kernel<<<dim3(HIDDEN / 32, 1024 / 32, NUM_OPS), 256>>>(W2, w2t, 1024);
    }

    dim3 grid(HIDDEN / BN, BATCH / BM, NUM_OPS);
    gemm_tc<1><<<grid, NTHREADS, DYN_SMEM>>>(b1, nullptr);
    gemm_tc<2><<<grid, NTHREADS, DYN_SMEM>>>(b2, out);
}